// round 1
// baseline (speedup 1.0000x reference)
#include <cuda_runtime.h>
#include <cuda_bf16.h>
#include <cstdint>

#define BB 512
#define THIST 512
#define HENC 256
#define HH 256
#define AA 256
#define TPRED 32
#define NG 1024  // 4*H

// ---------------- device scratch (static allocations only) ----------------
__device__ float g_enc_proj[(size_t)BB * THIST * AA];   // 268 MB
__device__ float g_Wt_enc[HENC * AA];                   // [a][e]
__device__ float g_Wt_dec[HH * AA];                     // [a][h]
__device__ float g_Wcat0[NG * 512];                     // [n][ {W_ih0[:,1:257] | W_hh0} ]
__device__ float g_Wcat1[NG * 512];                     // [n][ {W_ih1 | W_hh1} ]
__device__ float g_wcol0[NG];                           // W_ih0[:,0]
__device__ float g_bias0[NG];                           // b_ih0+b_hh0
__device__ float g_bias1[NG];
__device__ float g_h0[BB * HH], g_h1[BB * HH];
__device__ float g_c0[BB * HH], g_c1[BB * HH];
__device__ float g_ctx[BB * HENC];
__device__ float g_dec_in[BB];
__device__ float g_xcat0[BB * 512];                     // [ctx | h0_old]
__device__ float g_xcat1[BB * 512];                     // [h0_new | h1_old]
__device__ float g_xcatfc[BB * 512];                    // [h1_new | ctx]
__device__ float g_gates[BB * NG];
__device__ float g_dpart[2 * BB * AA];                  // dec_proj split-K partials
__device__ float g_fcpart[4 * BB * HH];                 // fc1 split-K partials

// ---------------- helpers ----------------
__device__ __forceinline__ float ftanh_fast(float x) {
    float y;
    asm("tanh.approx.f32 %0, %1;" : "=f"(y) : "f"(x));
    return y;
}

// ---------------- init + prep ----------------
__global__ void init_state(const float* __restrict__ eh, const float* __restrict__ ec) {
    int i = blockIdx.x * blockDim.x + threadIdx.x;
    if (i < BB * HH) {
        g_h0[i] = eh[i];
        g_h1[i] = eh[BB * HH + i];
        g_c0[i] = ec[i];
        g_c1[i] = ec[BB * HH + i];
    }
    if (i < BB) g_dec_in[i] = 0.f;
}

__global__ void prep(const float* __restrict__ Wae, const float* __restrict__ Wad,
                     const float* __restrict__ Wih0, const float* __restrict__ Whh0,
                     const float* __restrict__ bih0, const float* __restrict__ bhh0,
                     const float* __restrict__ Wih1, const float* __restrict__ Whh1,
                     const float* __restrict__ bih1, const float* __restrict__ bhh1) {
    int i = blockIdx.x * blockDim.x + threadIdx.x;
    if (i < HENC * AA) {
        int a = i / HENC, e = i % HENC;
        g_Wt_enc[i] = Wae[e * AA + a];
        g_Wt_dec[i] = Wad[e * AA + a];
    }
    if (i < NG * 512) {
        int n = i >> 9, c = i & 511;
        g_Wcat0[i] = (c < 256) ? Wih0[n * 257 + 1 + c] : Whh0[n * 256 + (c - 256)];
        g_Wcat1[i] = (c < 256) ? Wih1[n * 256 + c] : Whh1[n * 256 + (c - 256)];
    }
    if (i < NG) {
        g_wcol0[i] = Wih0[i * 257];
        g_bias0[i] = bih0[i] + bhh0[i];
        g_bias1[i] = bih1[i] + bhh1[i];
    }
}

// ---------------- generic C = A * B^T tiled GEMM (fp32) ----------------
// A: [M,K] lda, B: [N,K] ldb, C(+z*M*N): [M,N]. 64x64 tile, 256 thr, 4x4 micro.
__global__ __launch_bounds__(256) void gemm_abt(
    const float* __restrict__ Aa, const float* __restrict__ Bb, float* __restrict__ C,
    int M, int N, int K, int lda, int ldb, int klen) {
    __shared__ float As[16][68];
    __shared__ float Bs[16][68];
    const int m0 = blockIdx.y * 64;
    const int n0 = blockIdx.x * 64;
    const int kbeg = blockIdx.z * klen;
    const int tid = threadIdx.x;
    const int lr = tid >> 2;
    const int lc = (tid & 3) * 4;
    const int tx = tid & 15, ty = tid >> 4;
    const float* Ap = Aa + (size_t)(m0 + lr) * lda + kbeg + lc;
    const float* Bp = Bb + (size_t)(n0 + lr) * ldb + kbeg + lc;
    float acc[4][4];
#pragma unroll
    for (int i = 0; i < 4; i++)
#pragma unroll
        for (int j = 0; j < 4; j++) acc[i][j] = 0.f;
    for (int kt = 0; kt < klen; kt += 16) {
        float4 av = *(const float4*)(Ap + kt);
        float4 bv = *(const float4*)(Bp + kt);
        __syncthreads();
        As[lc + 0][lr] = av.x; As[lc + 1][lr] = av.y;
        As[lc + 2][lr] = av.z; As[lc + 3][lr] = av.w;
        Bs[lc + 0][lr] = bv.x; Bs[lc + 1][lr] = bv.y;
        Bs[lc + 2][lr] = bv.z; Bs[lc + 3][lr] = bv.w;
        __syncthreads();
#pragma unroll
        for (int kk = 0; kk < 16; kk++) {
            float ar[4], br[4];
#pragma unroll
            for (int i = 0; i < 4; i++) ar[i] = As[kk][ty * 4 + i];
#pragma unroll
            for (int j = 0; j < 4; j++) br[j] = Bs[kk][tx * 4 + j];
#pragma unroll
            for (int i = 0; i < 4; i++)
#pragma unroll
                for (int j = 0; j < 4; j++) acc[i][j] = fmaf(ar[i], br[j], acc[i][j]);
        }
    }
    float* Cp = C + (size_t)blockIdx.z * M * N;
#pragma unroll
    for (int i = 0; i < 4; i++) {
        int m = m0 + ty * 4 + i;
#pragma unroll
        for (int j = 0; j < 4; j++) Cp[(size_t)m * N + n0 + tx * 4 + j] = acc[i][j];
    }
}

// ---------------- fused attention (per step): one CTA per batch row ----------------
// score -> softmax -> attn write -> ctx; also builds xcat0 = [ctx|h0] and xcatfc[256:]=ctx
__global__ __launch_bounds__(256) void attn_step(
    const float* __restrict__ enc_out, const float* __restrict__ v,
    float* __restrict__ attn_out) {
    __shared__ float s_dp[256];
    __shared__ float s_v[256];
    __shared__ float s_sc[512];
    __shared__ float s_red[8];
    const int b = blockIdx.x;
    const int tid = threadIdx.x;
    const int lane = tid & 31, w = tid >> 5;

    s_dp[tid] = g_dpart[b * 256 + tid] + g_dpart[BB * 256 + b * 256 + tid];
    s_v[tid] = v[tid];
    __syncthreads();

    float vr[8], dr[8];
#pragma unroll
    for (int i = 0; i < 8; i++) {
        vr[i] = s_v[lane * 8 + i];
        dr[i] = s_dp[lane * 8 + i];
    }

    const float* ep = g_enc_proj + (size_t)b * THIST * AA;
    for (int t = w; t < THIST; t += 8) {
        const float4* row = (const float4*)(ep + (size_t)t * AA + lane * 8);
        float4 x0 = row[0];
        float4 x1 = row[1];
        float xs[8] = {x0.x, x0.y, x0.z, x0.w, x1.x, x1.y, x1.z, x1.w};
        float sum = 0.f;
#pragma unroll
        for (int i = 0; i < 8; i++) sum = fmaf(vr[i], ftanh_fast(xs[i] + dr[i]), sum);
#pragma unroll
        for (int off = 16; off; off >>= 1) sum += __shfl_xor_sync(0xffffffffu, sum, off);
        if (lane == 0) s_sc[t] = sum;
    }
    __syncthreads();

    // softmax over 512 scores
    float m = fmaxf(s_sc[tid], s_sc[tid + 256]);
#pragma unroll
    for (int off = 16; off; off >>= 1) m = fmaxf(m, __shfl_xor_sync(0xffffffffu, m, off));
    if (lane == 0) s_red[w] = m;
    __syncthreads();
    float mm = s_red[0];
#pragma unroll
    for (int i = 1; i < 8; i++) mm = fmaxf(mm, s_red[i]);
    float e0 = __expf(s_sc[tid] - mm);
    float e1 = __expf(s_sc[tid + 256] - mm);
    float sm = e0 + e1;
#pragma unroll
    for (int off = 16; off; off >>= 1) sm += __shfl_xor_sync(0xffffffffu, sm, off);
    __syncthreads();
    if (lane == 0) s_red[w] = sm;
    __syncthreads();
    float tot = s_red[0];
#pragma unroll
    for (int i = 1; i < 8; i++) tot += s_red[i];
    float inv = 1.f / tot;
    float p0 = e0 * inv, p1 = e1 * inv;
    s_sc[tid] = p0;
    s_sc[tid + 256] = p1;
    attn_out[(size_t)b * THIST + tid] = p0;
    attn_out[(size_t)b * THIST + tid + 256] = p1;
    __syncthreads();

    // ctx[e] = sum_t p[t]*enc_out[b,t,e]
    const float* eo = enc_out + (size_t)b * THIST * HENC;
    float c0 = 0.f, c1 = 0.f, c2 = 0.f, c3 = 0.f;
#pragma unroll 2
    for (int t = 0; t < THIST; t += 4) {
        c0 = fmaf(s_sc[t + 0], eo[(size_t)(t + 0) * HENC + tid], c0);
        c1 = fmaf(s_sc[t + 1], eo[(size_t)(t + 1) * HENC + tid], c1);
        c2 = fmaf(s_sc[t + 2], eo[(size_t)(t + 2) * HENC + tid], c2);
        c3 = fmaf(s_sc[t + 3], eo[(size_t)(t + 3) * HENC + tid], c3);
    }
    float cacc = (c0 + c1) + (c2 + c3);
    g_ctx[b * HENC + tid] = cacc;
    g_xcat0[b * 512 + tid] = cacc;
    g_xcat0[b * 512 + 256 + tid] = g_h0[b * 256 + tid];
    g_xcatfc[b * 512 + 256 + tid] = cacc;
}

// ---------------- LSTM cell updates (precise math; tiny op count) ----------------
__device__ __forceinline__ float sig_precise(float x) { return 1.f / (1.f + expf(-x)); }

__global__ __launch_bounds__(256) void cell0_kernel() {
    int idx = blockIdx.x * blockDim.x + threadIdx.x;  // b*256+j
    int b = idx >> 8, j = idx & 255;
    float extra = g_dec_in[b];
    const float* gb = g_gates + (size_t)b * NG;
    float gi = gb[j]       + extra * g_wcol0[j]       + g_bias0[j];
    float gf = gb[256 + j] + extra * g_wcol0[256 + j] + g_bias0[256 + j];
    float gg = gb[512 + j] + extra * g_wcol0[512 + j] + g_bias0[512 + j];
    float go = gb[768 + j] + extra * g_wcol0[768 + j] + g_bias0[768 + j];
    float c = sig_precise(gf) * g_c0[idx] + sig_precise(gi) * tanhf(gg);
    float h = sig_precise(go) * tanhf(c);
    g_c0[idx] = c;
    g_h0[idx] = h;
    g_xcat1[b * 512 + j] = h;
    g_xcat1[b * 512 + 256 + j] = g_h1[idx];  // old h1
}

__global__ __launch_bounds__(256) void cell1_kernel() {
    int idx = blockIdx.x * blockDim.x + threadIdx.x;
    int b = idx >> 8, j = idx & 255;
    const float* gb = g_gates + (size_t)b * NG;
    float gi = gb[j] + g_bias1[j];
    float gf = gb[256 + j] + g_bias1[256 + j];
    float gg = gb[512 + j] + g_bias1[512 + j];
    float go = gb[768 + j] + g_bias1[768 + j];
    float c = sig_precise(gf) * g_c1[idx] + sig_precise(gi) * tanhf(gg);
    float h = sig_precise(go) * tanhf(c);
    g_c1[idx] = c;
    g_h1[idx] = h;
    g_xcatfc[b * 512 + j] = h;
}

// ---------------- fc epilogue: sum split-K partials, relu, dot W_fc2 ----------------
__global__ __launch_bounds__(256) void fc_out_kernel(
    const float* __restrict__ bfc1, const float* __restrict__ Wfc2,
    const float* __restrict__ bfc2, float* __restrict__ outs, int s) {
    __shared__ float sr[8];
    int b = blockIdx.x, tid = threadIdx.x;
    int lane = tid & 31, w = tid >> 5;
    float vsum = g_fcpart[b * 256 + tid] + g_fcpart[BB * 256 + b * 256 + tid] +
                 g_fcpart[2 * BB * 256 + b * 256 + tid] + g_fcpart[3 * BB * 256 + b * 256 + tid];
    vsum += bfc1[tid];
    vsum = fmaxf(vsum, 0.f);
    float prod = vsum * Wfc2[tid];
#pragma unroll
    for (int off = 16; off; off >>= 1) prod += __shfl_xor_sync(0xffffffffu, prod, off);
    if (lane == 0) sr[w] = prod;
    __syncthreads();
    if (tid == 0) {
        float o = sr[0] + sr[1] + sr[2] + sr[3] + sr[4] + sr[5] + sr[6] + sr[7] + bfc2[0];
        outs[b * TPRED + s] = o;
        g_dec_in[b] = o;
    }
}

// ---------------- host launcher ----------------
extern "C" void kernel_launch(void* const* d_in, const int* in_sizes, int n_in,
                              void* d_out, int out_size) {
    // input order per setup_inputs: target_len (int scalar) may or may not be first tensor
    int off = (in_sizes[0] == 1) ? 1 : 0;
    const float* enc_out = (const float*)d_in[off + 0];
    const float* enc_h = (const float*)d_in[off + 1];
    const float* enc_c = (const float*)d_in[off + 2];
    const float* Wae = (const float*)d_in[off + 3];
    const float* Wad = (const float*)d_in[off + 4];
    const float* v = (const float*)d_in[off + 5];
    const float* Wih0 = (const float*)d_in[off + 6];
    const float* Whh0 = (const float*)d_in[off + 7];
    const float* bih0 = (const float*)d_in[off + 8];
    const float* bhh0 = (const float*)d_in[off + 9];
    const float* Wih1 = (const float*)d_in[off + 10];
    const float* Whh1 = (const float*)d_in[off + 11];
    const float* bih1 = (const float*)d_in[off + 12];
    const float* bhh1 = (const float*)d_in[off + 13];
    const float* Wfc1 = (const float*)d_in[off + 14];
    const float* bfc1 = (const float*)d_in[off + 15];
    const float* Wfc2 = (const float*)d_in[off + 16];
    const float* bfc2 = (const float*)d_in[off + 17];

    float* out = (float*)d_out;
    float* attn_base = out + (size_t)BB * TPRED;

    // device-global addresses (query only; no allocation)
    float *p_encproj, *p_Wtenc, *p_Wtdec, *p_Wcat0, *p_Wcat1;
    float *p_h1, *p_xcat0, *p_xcat1, *p_xcatfc, *p_gates, *p_dpart, *p_fcpart;
    cudaGetSymbolAddress((void**)&p_encproj, g_enc_proj);
    cudaGetSymbolAddress((void**)&p_Wtenc, g_Wt_enc);
    cudaGetSymbolAddress((void**)&p_Wtdec, g_Wt_dec);
    cudaGetSymbolAddress((void**)&p_Wcat0, g_Wcat0);
    cudaGetSymbolAddress((void**)&p_Wcat1, g_Wcat1);
    cudaGetSymbolAddress((void**)&p_h1, g_h1);
    cudaGetSymbolAddress((void**)&p_xcat0, g_xcat0);
    cudaGetSymbolAddress((void**)&p_xcat1, g_xcat1);
    cudaGetSymbolAddress((void**)&p_xcatfc, g_xcatfc);
    cudaGetSymbolAddress((void**)&p_gates, g_gates);
    cudaGetSymbolAddress((void**)&p_dpart, g_dpart);
    cudaGetSymbolAddress((void**)&p_fcpart, g_fcpart);

    init_state<<<(BB * HH + 255) / 256, 256>>>(enc_h, enc_c);
    prep<<<2048, 256>>>(Wae, Wad, Wih0, Whh0, bih0, bhh0, Wih1, Whh1, bih1, bhh1);

    // enc_proj = encoder_outputs @ W_att_enc   (M=B*T, N=A, K=H_enc)
    gemm_abt<<<dim3(4, 4096, 1), 256>>>(enc_out, p_Wtenc, p_encproj,
                                        BB * THIST, AA, HENC, HENC, HENC, HENC);

    for (int s = 0; s < TPRED; s++) {
        // dec_proj = h1 @ W_att_dec  (split-K=2)
        gemm_abt<<<dim3(4, 8, 2), 256>>>(p_h1, p_Wtdec, p_dpart,
                                         BB, AA, HH, HH, HH, HH / 2);
        // fused attention: scores + softmax + attn write + ctx
        attn_step<<<BB, 256>>>(enc_out, v, attn_base + (size_t)s * BB * THIST);
        // LSTM layer 0 gates: [ctx|h0] @ Wcat0^T
        gemm_abt<<<dim3(16, 8, 1), 256>>>(p_xcat0, p_Wcat0, p_gates,
                                          BB, NG, 512, 512, 512, 512);
        cell0_kernel<<<(BB * HH) / 256, 256>>>();
        // LSTM layer 1 gates: [h0'|h1] @ Wcat1^T
        gemm_abt<<<dim3(16, 8, 1), 256>>>(p_xcat1, p_Wcat1, p_gates,
                                          BB, NG, 512, 512, 512, 512);
        cell1_kernel<<<(BB * HH) / 256, 256>>>();
        // fc1: [h1'|ctx] @ W_fc1^T (split-K=4)
        gemm_abt<<<dim3(4, 8, 4), 256>>>(p_xcatfc, Wfc1, p_fcpart,
                                         BB, HH, 512, 512, 512, 128);
        fc_out_kernel<<<BB, 256>>>(bfc1, Wfc2, bfc2, out, s);
    }
    (void)n_in;
    (void)out_size;
}